// round 1
// baseline (speedup 1.0000x reference)
#include <cuda_runtime.h>
#include <cuda_bf16.h>
#include <math.h>

// Problem constants
#define B_SZ 8192
#define KDIM 1024   // IN_DIM == HID == 1024
#define NDIM 1024   // HID
#define ODE_STEPS 6

// ---------------- scratch (device globals; no runtime allocation) -----------
static __device__ float g_h0[(size_t)B_SZ * NDIM];      // h ping
static __device__ float g_h1[(size_t)B_SZ * NDIM];      // h pong
static __device__ float g_idrive[(size_t)B_SZ * NDIM];  // x @ W_in^T + b_in
static __device__ float g_gatex[(size_t)B_SZ * NDIM];   // x @ Wg_x^T + b_g
static __device__ float g_drivet[(size_t)B_SZ * NDIM];  // tanh(idrive + h @ W_rec^T)
static __device__ float g_scale[NDIM];                  // (1/6) * exp(-log_tau)

// ---------------- tiny kernels ----------------------------------------------
__global__ void scale_kernel(const float* __restrict__ log_tau, float* __restrict__ scale) {
    int i = blockIdx.x * blockDim.x + threadIdx.x;
    if (i < NDIM) scale[i] = (1.0f / 6.0f) * expf(-log_tau[i]);
}

__global__ void copy_out_kernel(const float* __restrict__ h, float* __restrict__ out,
                                size_t n, int dup) {
    size_t i = (size_t)blockIdx.x * blockDim.x + threadIdx.x;
    size_t i4 = i * 4;
    if (i4 < n) {
        float4 v = *(const float4*)(h + i4);
        *(float4*)(out + i4) = v;
        if (dup) *(float4*)(out + n + i4) = v;
    }
}

// ---------------- fused GEMM -------------------------------------------------
// C[m,n] = sum_k A[m,k] * W[n,k]   (A: [B_SZ x KDIM] row-major, W rows stride ldw)
// MODE 0: C = acc + bias[n]                                   (p0 = bias)
// MODE 1: C = tanh(p0[m,n] + acc)                             (p0 = input_drive)
// MODE 2: gate = sigmoid(p0[m,n] + acc); d = p1[m,n];
//         hv = A[m,n];  C = hv + p2[n] * (gate*d - hv)        (p0=gate_x, p1=drive_t, p2=scale)
template <int MODE>
__global__ __launch_bounds__(256, 2)
void gemm_kernel(const float* __restrict__ A, const float* __restrict__ W, int ldw,
                 const float* __restrict__ p0, const float* __restrict__ p1,
                 const float* __restrict__ p2, float* __restrict__ C) {
    constexpr int BM = 128, BN = 128, BK = 16;
    constexpr int PAD = 4;  // kill STS bank conflicts, keep float4 alignment
    __shared__ float As[2][BK][BM + PAD];
    __shared__ float Bs[2][BK][BN + PAD];

    const int tid = threadIdx.x;
    const int tx = tid & 15;       // 0..15 -> n groups
    const int ty = tid >> 4;       // 0..15 -> m groups
    const int mBase = blockIdx.y * BM;
    const int nBase = blockIdx.x * BN;

    const float* Aop = A + (size_t)mBase * KDIM;
    const float* Wop = W + (size_t)nBase * ldw;

    const int lrow = tid >> 2;          // 0..63
    const int lk4  = (tid & 3) * 4;     // 0,4,8,12

    float acc[8][8];
#pragma unroll
    for (int i = 0; i < 8; i++)
#pragma unroll
        for (int j = 0; j < 8; j++) acc[i][j] = 0.0f;

    float4 aReg[2], bReg[2];

    // prologue: load k-tile 0
#pragma unroll
    for (int i = 0; i < 2; i++) {
        int r = lrow + i * 64;
        aReg[i] = *(const float4*)(Aop + (size_t)r * KDIM + lk4);
        bReg[i] = *(const float4*)(Wop + (size_t)r * ldw + lk4);
    }
#pragma unroll
    for (int i = 0; i < 2; i++) {
        int r = lrow + i * 64;
        As[0][lk4 + 0][r] = aReg[i].x; As[0][lk4 + 1][r] = aReg[i].y;
        As[0][lk4 + 2][r] = aReg[i].z; As[0][lk4 + 3][r] = aReg[i].w;
        Bs[0][lk4 + 0][r] = bReg[i].x; Bs[0][lk4 + 1][r] = bReg[i].y;
        Bs[0][lk4 + 2][r] = bReg[i].z; Bs[0][lk4 + 3][r] = bReg[i].w;
    }
    __syncthreads();

    int buf = 0;
    const int NKT = KDIM / BK;  // 64
    for (int kt = 0; kt < NKT; kt++) {
        // prefetch next k-tile into registers
        if (kt + 1 < NKT) {
            int k0n = (kt + 1) * BK;
#pragma unroll
            for (int i = 0; i < 2; i++) {
                int r = lrow + i * 64;
                aReg[i] = *(const float4*)(Aop + (size_t)r * KDIM + k0n + lk4);
                bReg[i] = *(const float4*)(Wop + (size_t)r * ldw + k0n + lk4);
            }
        }
        // compute on current buffer
#pragma unroll
        for (int k = 0; k < BK; k++) {
            float4 a0 = *(const float4*)&As[buf][k][ty * 4];
            float4 a1 = *(const float4*)&As[buf][k][ty * 4 + 64];
            float4 b0 = *(const float4*)&Bs[buf][k][tx * 4];
            float4 b1 = *(const float4*)&Bs[buf][k][tx * 4 + 64];
            float av[8] = {a0.x, a0.y, a0.z, a0.w, a1.x, a1.y, a1.z, a1.w};
            float bv[8] = {b0.x, b0.y, b0.z, b0.w, b1.x, b1.y, b1.z, b1.w};
#pragma unroll
            for (int i = 0; i < 8; i++)
#pragma unroll
                for (int j = 0; j < 8; j++) acc[i][j] = fmaf(av[i], bv[j], acc[i][j]);
        }
        // write next tile, flip
        if (kt + 1 < NKT) {
            int nb = buf ^ 1;
#pragma unroll
            for (int i = 0; i < 2; i++) {
                int r = lrow + i * 64;
                As[nb][lk4 + 0][r] = aReg[i].x; As[nb][lk4 + 1][r] = aReg[i].y;
                As[nb][lk4 + 2][r] = aReg[i].z; As[nb][lk4 + 3][r] = aReg[i].w;
                Bs[nb][lk4 + 0][r] = bReg[i].x; Bs[nb][lk4 + 1][r] = bReg[i].y;
                Bs[nb][lk4 + 2][r] = bReg[i].z; Bs[nb][lk4 + 3][r] = bReg[i].w;
            }
            __syncthreads();
            buf = nb;
        }
    }

    // epilogue
    int mIdx[8], nIdx[8];
#pragma unroll
    for (int i = 0; i < 4; i++) {
        mIdx[i]     = mBase + ty * 4 + i;
        mIdx[4 + i] = mBase + 64 + ty * 4 + i;
        nIdx[i]     = nBase + tx * 4 + i;
        nIdx[4 + i] = nBase + 64 + tx * 4 + i;
    }

#pragma unroll
    for (int i = 0; i < 8; i++) {
#pragma unroll
        for (int j = 0; j < 8; j++) {
            size_t idx = (size_t)mIdx[i] * NDIM + nIdx[j];
            float v = acc[i][j];
            if (MODE == 0) {
                C[idx] = v + p0[nIdx[j]];
            } else if (MODE == 1) {
                C[idx] = tanhf(p0[idx] + v);
            } else {  // MODE == 2
                float pre = p0[idx] + v;
                float g = 1.0f / (1.0f + expf(-pre));
                float d = p1[idx];
                float hv = A[(size_t)mIdx[i] * KDIM + nIdx[j]];
                C[idx] = hv + p2[nIdx[j]] * (g * d - hv);
            }
        }
    }
}

// ---------------- launch -----------------------------------------------------
extern "C" void kernel_launch(void* const* d_in, const int* in_sizes, int n_in,
                              void* d_out, int out_size) {
    const float* x       = (const float*)d_in[0];
    const float* h_in    = (const float*)d_in[1];
    const float* log_tau = (const float*)d_in[2];
    const float* W_in_w  = (const float*)d_in[3];
    const float* W_in_b  = (const float*)d_in[4];
    const float* W_rec_w = (const float*)d_in[5];
    const float* W_gate_w= (const float*)d_in[6];
    const float* W_gate_b= (const float*)d_in[7];
    (void)in_sizes; (void)n_in;

    float *ph0, *ph1, *pid, *pgx, *pdt, *psc;
    cudaGetSymbolAddress((void**)&ph0, g_h0);
    cudaGetSymbolAddress((void**)&ph1, g_h1);
    cudaGetSymbolAddress((void**)&pid, g_idrive);
    cudaGetSymbolAddress((void**)&pgx, g_gatex);
    cudaGetSymbolAddress((void**)&pdt, g_drivet);
    cudaGetSymbolAddress((void**)&psc, g_scale);

    const size_t n = (size_t)B_SZ * NDIM;

    // copy initial h into scratch (inputs must not be modified across graph replays)
    cudaMemcpyAsync(ph0, h_in, n * sizeof(float), cudaMemcpyDeviceToDevice, 0);
    scale_kernel<<<(NDIM + 255) / 256, 256>>>(log_tau, psc);

    dim3 grid(NDIM / 128, B_SZ / 128);  // (8, 64)

    // precompute: input_drive and gate_x
    gemm_kernel<0><<<grid, 256>>>(x, W_in_w, KDIM, W_in_b, nullptr, nullptr, pid);
    gemm_kernel<0><<<grid, 256>>>(x, W_gate_w, 2 * KDIM, W_gate_b, nullptr, nullptr, pgx);

    float* hb[2] = {ph0, ph1};
    for (int s = 0; s < ODE_STEPS; s++) {
        const float* hcur = hb[s & 1];
        float* hnext = hb[(s + 1) & 1];
        // drive_t = tanh(input_drive + h @ W_rec^T)
        gemm_kernel<1><<<grid, 256>>>(hcur, W_rec_w, KDIM, pid, nullptr, nullptr, pdt);
        // fused gate GEMM + state update
        gemm_kernel<2><<<grid, 256>>>(hcur, W_gate_w + KDIM, 2 * KDIM, pgx, pdt, psc, hnext);
    }

    // after 6 steps (even), result is in g_h0
    int dup = ((size_t)out_size >= 2 * n) ? 1 : 0;
    size_t nv4 = n / 4;
    copy_out_kernel<<<(unsigned)((nv4 + 255) / 256), 256>>>(ph0, (float*)d_out, n, dup);
}

// round 3
// speedup vs baseline: 4.4864x; 4.4864x over previous
#include <cuda_runtime.h>
#include <cuda_fp16.h>
#include <cstdint>
#include <math.h>

// ---------------- problem constants ----------------
#define B_SZ 8192
#define KDIM 1024
#define NDIM 1024
#define ODE_STEPS 6

// ---------------- GEMM config ----------------
#define BM 128
#define BN 128
#define KT 64                         // K elems per pipeline chunk (fp16: 128 B/row)
#define NCH (KDIM / KT)               // 16 chunks
#define STAGES 3
#define A_STAGE_BYTES (BM * KT * 2)   // 16 KB
#define STAGE_BYTES (2 * A_STAGE_BYTES)
#define SMEM_TOTAL (STAGES * STAGE_BYTES)  // 96 KB
#define NTHREADS 512

// ---------------- scratch (device globals; no runtime allocation) -----------
static __device__ float  g_h0[(size_t)B_SZ * NDIM];     // exact h ping
static __device__ float  g_h1[(size_t)B_SZ * NDIM];     // exact h pong
static __device__ __half g_hh0[(size_t)B_SZ * NDIM];    // fp16 h ping
static __device__ __half g_hh1[(size_t)B_SZ * NDIM];    // fp16 h pong
static __device__ float  g_idrive[(size_t)B_SZ * NDIM];
static __device__ float  g_gatex[(size_t)B_SZ * NDIM];
static __device__ float  g_drivet[(size_t)B_SZ * NDIM];
static __device__ __half g_xh[(size_t)B_SZ * KDIM];     // fp16 x
static __device__ __half g_winh[(size_t)NDIM * KDIM];
static __device__ __half g_wrech[(size_t)NDIM * KDIM];
static __device__ __half g_wgxh[(size_t)NDIM * KDIM];
static __device__ __half g_wghh[(size_t)NDIM * KDIM];
static __device__ float  g_scale[NDIM];                 // (1/6)*exp(-log_tau)

// ---------------- helpers ----------------
__device__ __forceinline__ uint32_t swz128(uint32_t off) { return off ^ ((off >> 3) & 0x70); }

__device__ __forceinline__ void cp16(uint32_t s, const void* g) {
    asm volatile("cp.async.cg.shared.global [%0], [%1], 16;" :: "r"(s), "l"(g) : "memory");
}
__device__ __forceinline__ void ldsm4(uint32_t* r, uint32_t addr) {
    asm volatile("ldmatrix.sync.aligned.m8n8.x4.shared.b16 {%0,%1,%2,%3}, [%4];"
                 : "=r"(r[0]), "=r"(r[1]), "=r"(r[2]), "=r"(r[3]) : "r"(addr));
}
__device__ __forceinline__ void mma16816(float* d, const uint32_t* a, const uint32_t* b) {
    asm volatile(
        "mma.sync.aligned.m16n8k16.row.col.f32.f16.f16.f32 "
        "{%0,%1,%2,%3}, {%4,%5,%6,%7}, {%8,%9}, {%0,%1,%2,%3};"
        : "+f"(d[0]), "+f"(d[1]), "+f"(d[2]), "+f"(d[3])
        : "r"(a[0]), "r"(a[1]), "r"(a[2]), "r"(a[3]), "r"(b[0]), "r"(b[1]));
}

// ---------------- prep kernels ----------------
__global__ void tohalf_kernel(const float* __restrict__ src, __half* __restrict__ dst, int n4) {
    int i = blockIdx.x * blockDim.x + threadIdx.x;
    if (i < n4) {
        float4 v = ((const float4*)src)[i];
        __half2 h0 = __floats2half2_rn(v.x, v.y);
        __half2 h1 = __floats2half2_rn(v.z, v.w);
        ((__half2*)dst)[2 * i]     = h0;
        ((__half2*)dst)[2 * i + 1] = h1;
    }
}
__global__ void gate_split_half(const float* __restrict__ Wg,
                                __half* __restrict__ wgx, __half* __restrict__ wgh) {
    int i = blockIdx.x * blockDim.x + threadIdx.x;  // over (1024*1024)/4 float4
    if (i < (NDIM * KDIM) / 4) {
        int i4 = i * 4;
        int row = i4 >> 10, col = i4 & 1023;
        const float4 vx = *(const float4*)(Wg + (size_t)row * 2048 + col);
        const float4 vh = *(const float4*)(Wg + (size_t)row * 2048 + 1024 + col);
        ((__half2*)wgx)[2 * i]     = __floats2half2_rn(vx.x, vx.y);
        ((__half2*)wgx)[2 * i + 1] = __floats2half2_rn(vx.z, vx.w);
        ((__half2*)wgh)[2 * i]     = __floats2half2_rn(vh.x, vh.y);
        ((__half2*)wgh)[2 * i + 1] = __floats2half2_rn(vh.z, vh.w);
    }
}
__global__ void scale_kernel(const float* __restrict__ log_tau, float* __restrict__ scale) {
    int i = blockIdx.x * blockDim.x + threadIdx.x;
    if (i < NDIM) scale[i] = (1.0f / 6.0f) * expf(-log_tau[i]);
}
__global__ void copy_out_kernel(const float* __restrict__ h, float* __restrict__ out,
                                size_t n, int dup) {
    size_t i = (size_t)blockIdx.x * blockDim.x + threadIdx.x;
    size_t i4 = i * 4;
    if (i4 < n) {
        float4 v = *(const float4*)(h + i4);
        *(float4*)(out + i4) = v;
        if (dup) *(float4*)(out + n + i4) = v;
    }
}

// ---------------- fp16 tensor-core GEMM with fused epilogue ----------------
// acc[m,n] = sum_k A[m,k]*W[n,k]  (A,W fp16; accumulate fp32)
// MODE 0: C = acc + p0[n]
// MODE 1: C = tanh(p0[idx] + acc)
// MODE 2: gate = sigmoid(p0[idx]+acc); C = hx + sc[n]*(gate*p1[idx]-hx); Cr = half(C)
template <int MODE>
__global__ void __launch_bounds__(NTHREADS, 1)
ltc_gemm(const __half* __restrict__ A, const __half* __restrict__ W,
         const float* __restrict__ p0, const float* __restrict__ p1,
         const float* __restrict__ hx, const float* __restrict__ sc,
         float* __restrict__ C, __half* __restrict__ Cr) {
    extern __shared__ char dsm[];
    const uint32_t sbase = (uint32_t)__cvta_generic_to_shared(dsm);
    const int tid = threadIdx.x;
    const int wid = tid >> 5, lid = tid & 31;
    const int wm = wid >> 2, wn = wid & 3;      // 4x4 warp grid; warp tile 32x32
    const int mBase = blockIdx.y * BM;
    const int nBase = blockIdx.x * BN;

    // loader: chunk c -> stage c%STAGES; 512 threads x 4 chunks (2 A + 2 B)
    auto load_chunk = [&](int c) {
        const uint32_t stA = sbase + (c % STAGES) * STAGE_BYTES;
        const uint32_t stB = stA + A_STAGE_BYTES;
        const __half* ga = A + (size_t)mBase * KDIM + c * KT;
        const __half* gb = W + (size_t)nBase * KDIM + c * KT;
#pragma unroll
        for (int i = 0; i < 2; i++) {
            int t = tid + i * NTHREADS;          // 0..1023
            int row = t >> 3, cg = t & 7;
            uint32_t sw = swz128((uint32_t)(row * 128 + cg * 16));
            cp16(stA + sw, ga + (size_t)row * KDIM + cg * 8);
            cp16(stB + sw, gb + (size_t)row * KDIM + cg * 8);
        }
        asm volatile("cp.async.commit_group;" ::: "memory");
    };

    float acc[2][4][4];
#pragma unroll
    for (int mt = 0; mt < 2; mt++)
#pragma unroll
        for (int nt = 0; nt < 4; nt++)
#pragma unroll
            for (int e = 0; e < 4; e++) acc[mt][nt][e] = 0.0f;

    load_chunk(0);
    load_chunk(1);

    const int sub = lid >> 3, li = lid & 7;

    for (int kt = 0; kt < NCH; kt++) {
        asm volatile("cp.async.wait_group 1;" ::: "memory");
        __syncthreads();
        if (kt + 2 < NCH) load_chunk(kt + 2);
        else asm volatile("cp.async.commit_group;" ::: "memory");

        const uint32_t tbA = sbase + (kt % STAGES) * STAGE_BYTES;
        const uint32_t tbB = tbA + A_STAGE_BYTES;
#pragma unroll
        for (int ks = 0; ks < 4; ks++) {
            const int k0 = ks * 16;
            uint32_t af[2][4], bf[2][4];
#pragma unroll
            for (int mt = 0; mt < 2; mt++) {
                int row = wm * 32 + mt * 16 + ((sub & 1) << 3) + li;
                int kb = (k0 + ((sub >> 1) << 3)) * 2;
                ldsm4(af[mt], tbA + swz128((uint32_t)(row * 128 + kb)));
            }
#pragma unroll
            for (int np = 0; np < 2; np++) {
                int row = wn * 32 + np * 16 + ((sub >> 1) << 3) + li;
                int kb = (k0 + ((sub & 1) << 3)) * 2;
                ldsm4(bf[np], tbB + swz128((uint32_t)(row * 128 + kb)));
            }
#pragma unroll
            for (int mt = 0; mt < 2; mt++)
#pragma unroll
                for (int nt = 0; nt < 4; nt++)
                    mma16816(acc[mt][nt], af[mt], &bf[nt >> 1][(nt & 1) * 2]);
        }
    }
    asm volatile("cp.async.wait_group 0;" ::: "memory");

    // ---------------- fused epilogue (register fragments -> global) ----------
    const int l4 = lid >> 2, l2 = (lid & 3) * 2;
#pragma unroll
    for (int mt = 0; mt < 2; mt++) {
#pragma unroll
        for (int nt = 0; nt < 4; nt++) {
            const int gr = mBase + wm * 32 + mt * 16 + l4;
            const int gc = nBase + wn * 32 + nt * 8 + l2;
            const float* a = acc[mt][nt];
#pragma unroll
            for (int half_ = 0; half_ < 2; half_++) {
                const int row = gr + half_ * 8;
                const size_t idx = (size_t)row * NDIM + gc;
                float vx = a[half_ * 2], vy = a[half_ * 2 + 1];
                float ox, oy;
                if (MODE == 0) {
                    float2 bv = *(const float2*)(p0 + gc);
                    ox = vx + bv.x; oy = vy + bv.y;
                } else if (MODE == 1) {
                    float2 pv = *(const float2*)(p0 + idx);
                    ox = tanhf(pv.x + vx); oy = tanhf(pv.y + vy);
                } else {
                    float2 pv = *(const float2*)(p0 + idx);
                    float2 dv = *(const float2*)(p1 + idx);
                    float2 hv = *(const float2*)(hx + idx);
                    float2 sv = *(const float2*)(sc + gc);
                    float gx = 1.0f / (1.0f + expf(-(pv.x + vx)));
                    float gy = 1.0f / (1.0f + expf(-(pv.y + vy)));
                    ox = hv.x + sv.x * (gx * dv.x - hv.x);
                    oy = hv.y + sv.y * (gy * dv.y - hv.y);
                }
                *(float2*)(C + idx) = make_float2(ox, oy);
                if (MODE == 2) *(__half2*)(Cr + idx) = __floats2half2_rn(ox, oy);
            }
        }
    }
}

// ---------------- launch ----------------
extern "C" void kernel_launch(void* const* d_in, const int* in_sizes, int n_in,
                              void* d_out, int out_size) {
    const float* x        = (const float*)d_in[0];
    const float* h_in     = (const float*)d_in[1];
    const float* log_tau  = (const float*)d_in[2];
    const float* W_in_w   = (const float*)d_in[3];
    const float* W_in_b   = (const float*)d_in[4];
    const float* W_rec_w  = (const float*)d_in[5];
    const float* W_gate_w = (const float*)d_in[6];
    const float* W_gate_b = (const float*)d_in[7];
    (void)in_sizes; (void)n_in;

    float *ph0, *ph1, *pid, *pgx, *pdt, *psc;
    __half *phh0, *phh1, *pxh, *pwinh, *pwrech, *pwgxh, *pwghh;
    cudaGetSymbolAddress((void**)&ph0, g_h0);
    cudaGetSymbolAddress((void**)&ph1, g_h1);
    cudaGetSymbolAddress((void**)&phh0, g_hh0);
    cudaGetSymbolAddress((void**)&phh1, g_hh1);
    cudaGetSymbolAddress((void**)&pid, g_idrive);
    cudaGetSymbolAddress((void**)&pgx, g_gatex);
    cudaGetSymbolAddress((void**)&pdt, g_drivet);
    cudaGetSymbolAddress((void**)&pxh, g_xh);
    cudaGetSymbolAddress((void**)&pwinh, g_winh);
    cudaGetSymbolAddress((void**)&pwrech, g_wrech);
    cudaGetSymbolAddress((void**)&pwgxh, g_wgxh);
    cudaGetSymbolAddress((void**)&pwghh, g_wghh);
    cudaGetSymbolAddress((void**)&psc, g_scale);

    cudaFuncSetAttribute(ltc_gemm<0>, cudaFuncAttributeMaxDynamicSharedMemorySize, SMEM_TOTAL);
    cudaFuncSetAttribute(ltc_gemm<1>, cudaFuncAttributeMaxDynamicSharedMemorySize, SMEM_TOTAL);
    cudaFuncSetAttribute(ltc_gemm<2>, cudaFuncAttributeMaxDynamicSharedMemorySize, SMEM_TOTAL);

    const size_t n = (size_t)B_SZ * NDIM;

    // prep: exact h copy, fp16 casts, per-channel scale
    cudaMemcpyAsync(ph0, h_in, n * sizeof(float), cudaMemcpyDeviceToDevice, 0);
    scale_kernel<<<(NDIM + 255) / 256, 256>>>(log_tau, psc);
    tohalf_kernel<<<(int)((n / 4 + 255) / 256), 256>>>(x, pxh, (int)(n / 4));
    tohalf_kernel<<<(int)((n / 4 + 255) / 256), 256>>>(h_in, phh0, (int)(n / 4));
    tohalf_kernel<<<(NDIM * KDIM / 4 + 255) / 256, 256>>>(W_in_w, pwinh, NDIM * KDIM / 4);
    tohalf_kernel<<<(NDIM * KDIM / 4 + 255) / 256, 256>>>(W_rec_w, pwrech, NDIM * KDIM / 4);
    gate_split_half<<<(NDIM * KDIM / 4 + 255) / 256, 256>>>(W_gate_w, pwgxh, pwghh);

    dim3 grid(NDIM / BN, B_SZ / BM);  // (8, 64) = 512 CTAs

    // precompute drives
    ltc_gemm<0><<<grid, NTHREADS, SMEM_TOTAL>>>(pxh, pwinh, W_in_b, nullptr, nullptr, nullptr, pid, nullptr);
    ltc_gemm<0><<<grid, NTHREADS, SMEM_TOTAL>>>(pxh, pwgxh, W_gate_b, nullptr, nullptr, nullptr, pgx, nullptr);

    float*  hb[2]  = {ph0, ph1};
    __half* hhb[2] = {phh0, phh1};
    for (int s = 0; s < ODE_STEPS; s++) {
        const __half* hh = hhb[s & 1];
        const float*  he = hb[s & 1];
        float*  hne = hb[(s + 1) & 1];
        __half* hnh = hhb[(s + 1) & 1];
        ltc_gemm<1><<<grid, NTHREADS, SMEM_TOTAL>>>(hh, pwrech, pid, nullptr, nullptr, nullptr, pdt, nullptr);
        ltc_gemm<2><<<grid, NTHREADS, SMEM_TOTAL>>>(hh, pwghh, pgx, pdt, he, psc, hne, hnh);
    }

    int dup = ((size_t)out_size >= 2 * n) ? 1 : 0;
    size_t nv4 = n / 4;
    copy_out_kernel<<<(unsigned)((nv4 + 255) / 256), 256>>>(ph0, (float*)d_out, n, dup);
}

// round 4
// speedup vs baseline: 5.8425x; 1.3023x over previous
#include <cuda_runtime.h>
#include <cuda_fp16.h>
#include <cstdint>
#include <math.h>

// ---------------- problem constants ----------------
#define B_SZ 8192
#define KDIM 1024
#define NDIM 1024
#define ODE_STEPS 6

// ---------------- GEMM config ----------------
#define BM 128
#define BN 128
#define KT 64                          // K elems per pipeline chunk (fp16: 128 B/row)
#define NCH (KDIM / KT)                // 16 chunks
#define STAGES 3
#define TILE_BYTES (BM * KT * 2)       // 16 KB per operand tile
#define STAGE_BYTES (3 * TILE_BYTES)   // A + B0 + B1 = 48 KB
#define SMEM_TOTAL (STAGES * STAGE_BYTES)  // 144 KB
#define NTHREADS 512

// ---------------- scratch (device globals; no runtime allocation) -----------
static __device__ float  g_h0[(size_t)B_SZ * NDIM];     // exact h ping
static __device__ float  g_h1[(size_t)B_SZ * NDIM];     // exact h pong
static __device__ __half g_hh0[(size_t)B_SZ * NDIM];    // fp16 h ping
static __device__ __half g_hh1[(size_t)B_SZ * NDIM];    // fp16 h pong
static __device__ float  g_idrive[(size_t)B_SZ * NDIM];
static __device__ float  g_gatex[(size_t)B_SZ * NDIM];
static __device__ __half g_xh[(size_t)B_SZ * KDIM];     // fp16 x
static __device__ __half g_winh[(size_t)NDIM * KDIM];
static __device__ __half g_wrech[(size_t)NDIM * KDIM];
static __device__ __half g_wgxh[(size_t)NDIM * KDIM];
static __device__ __half g_wghh[(size_t)NDIM * KDIM];
static __device__ float  g_scale[NDIM];                 // (1/6)*exp(-log_tau)

// ---------------- helpers ----------------
__device__ __forceinline__ uint32_t swz128(uint32_t off) { return off ^ ((off >> 3) & 0x70); }

__device__ __forceinline__ void cp16(uint32_t s, const void* g) {
    asm volatile("cp.async.cg.shared.global [%0], [%1], 16;" :: "r"(s), "l"(g) : "memory");
}
__device__ __forceinline__ void ldsm4(uint32_t* r, uint32_t addr) {
    asm volatile("ldmatrix.sync.aligned.m8n8.x4.shared.b16 {%0,%1,%2,%3}, [%4];"
                 : "=r"(r[0]), "=r"(r[1]), "=r"(r[2]), "=r"(r[3]) : "r"(addr));
}
__device__ __forceinline__ void mma16816(float* d, const uint32_t* a, const uint32_t* b) {
    asm volatile(
        "mma.sync.aligned.m16n8k16.row.col.f32.f16.f16.f32 "
        "{%0,%1,%2,%3}, {%4,%5,%6,%7}, {%8,%9}, {%0,%1,%2,%3};"
        : "+f"(d[0]), "+f"(d[1]), "+f"(d[2]), "+f"(d[3])
        : "r"(a[0]), "r"(a[1]), "r"(a[2]), "r"(a[3]), "r"(b[0]), "r"(b[1]));
}

// ---------------- prep kernels ----------------
__global__ void tohalf_kernel(const float* __restrict__ src, __half* __restrict__ dst, int n4) {
    int i = blockIdx.x * blockDim.x + threadIdx.x;
    if (i < n4) {
        float4 v = ((const float4*)src)[i];
        ((__half2*)dst)[2 * i]     = __floats2half2_rn(v.x, v.y);
        ((__half2*)dst)[2 * i + 1] = __floats2half2_rn(v.z, v.w);
    }
}
__global__ void gate_split_half(const float* __restrict__ Wg,
                                __half* __restrict__ wgx, __half* __restrict__ wgh) {
    int i = blockIdx.x * blockDim.x + threadIdx.x;
    if (i < (NDIM * KDIM) / 4) {
        int i4 = i * 4;
        int row = i4 >> 10, col = i4 & 1023;
        const float4 vx = *(const float4*)(Wg + (size_t)row * 2048 + col);
        const float4 vh = *(const float4*)(Wg + (size_t)row * 2048 + 1024 + col);
        ((__half2*)wgx)[2 * i]     = __floats2half2_rn(vx.x, vx.y);
        ((__half2*)wgx)[2 * i + 1] = __floats2half2_rn(vx.z, vx.w);
        ((__half2*)wgh)[2 * i]     = __floats2half2_rn(vh.x, vh.y);
        ((__half2*)wgh)[2 * i + 1] = __floats2half2_rn(vh.z, vh.w);
    }
}
__global__ void scale_kernel(const float* __restrict__ log_tau, float* __restrict__ scale) {
    int i = blockIdx.x * blockDim.x + threadIdx.x;
    if (i < NDIM) scale[i] = (1.0f / 6.0f) * expf(-log_tau[i]);
}

// ---------------- dual fp16 tensor-core GEMM with fully fused step ----------
// acc0[m,n] = sum_k A[m,k]*W0[n,k];  acc1[m,n] = sum_k A[m,k]*W1[n,k]
// MODE 0 (precompute): O0 = acc0 + e0[n];  O1 = acc1 + e1[n]
// MODE 1 (ODE step):   drive = tanh(e0[idx]+acc0); gate = sigmoid(e1[idx]+acc1);
//                      o = hx + sc[n]*(gate*drive - hx);  O0 = o; Oh = half(o)
// MODE 2 (last step):  same as 1 but O0 = o and O1 = o (duplicated output)
template <int MODE>
__global__ void __launch_bounds__(NTHREADS, 1)
ltc_fused(const __half* __restrict__ A, const __half* __restrict__ W0,
          const __half* __restrict__ W1,
          const float* __restrict__ e0, const float* __restrict__ e1,
          const float* __restrict__ hx, const float* __restrict__ sc,
          float* __restrict__ O0, float* __restrict__ O1, __half* __restrict__ Oh) {
    extern __shared__ char dsm[];
    const uint32_t sbase = (uint32_t)__cvta_generic_to_shared(dsm);
    const int tid = threadIdx.x;
    const int wid = tid >> 5, lid = tid & 31;
    const int wm = wid >> 2, wn = wid & 3;      // 4x4 warp grid; warp tile 32x32
    const int mBase = blockIdx.y * BM;
    const int nBase = blockIdx.x * BN;

    auto load_chunk = [&](int c) {
        const uint32_t st = sbase + (c % STAGES) * STAGE_BYTES;
        const __half* ga  = A  + (size_t)mBase * KDIM + c * KT;
        const __half* gb0 = W0 + (size_t)nBase * KDIM + c * KT;
        const __half* gb1 = W1 + (size_t)nBase * KDIM + c * KT;
#pragma unroll
        for (int i = 0; i < 2; i++) {
            int t = tid + i * NTHREADS;          // 0..1023
            int row = t >> 3, cg = t & 7;
            uint32_t sw = swz128((uint32_t)(row * 128 + cg * 16));
            size_t go = (size_t)row * KDIM + cg * 8;
            cp16(st + sw, ga + go);
            cp16(st + TILE_BYTES + sw, gb0 + go);
            cp16(st + 2 * TILE_BYTES + sw, gb1 + go);
        }
        asm volatile("cp.async.commit_group;" ::: "memory");
    };

    float acc0[2][4][4], acc1[2][4][4];
#pragma unroll
    for (int mt = 0; mt < 2; mt++)
#pragma unroll
        for (int nt = 0; nt < 4; nt++)
#pragma unroll
            for (int e = 0; e < 4; e++) { acc0[mt][nt][e] = 0.0f; acc1[mt][nt][e] = 0.0f; }

    load_chunk(0);
    load_chunk(1);

    const int sub = lid >> 3, li = lid & 7;

    for (int kt = 0; kt < NCH; kt++) {
        asm volatile("cp.async.wait_group 1;" ::: "memory");
        __syncthreads();
        if (kt + 2 < NCH) load_chunk(kt + 2);
        else asm volatile("cp.async.commit_group;" ::: "memory");

        const uint32_t tb = sbase + (kt % STAGES) * STAGE_BYTES;
#pragma unroll
        for (int ks = 0; ks < 4; ks++) {
            const int k0 = ks * 16;
            uint32_t af[2][4];
#pragma unroll
            for (int mt = 0; mt < 2; mt++) {
                int row = wm * 32 + mt * 16 + ((sub & 1) << 3) + li;
                int kb = (k0 + ((sub >> 1) << 3)) * 2;
                ldsm4(af[mt], tb + swz128((uint32_t)(row * 128 + kb)));
            }
            // B0 pass (bf registers reused across passes)
            {
                uint32_t bf[2][4];
#pragma unroll
                for (int np = 0; np < 2; np++) {
                    int row = wn * 32 + np * 16 + ((sub >> 1) << 3) + li;
                    int kb = (k0 + ((sub & 1) << 3)) * 2;
                    ldsm4(bf[np], tb + TILE_BYTES + swz128((uint32_t)(row * 128 + kb)));
                }
#pragma unroll
                for (int mt = 0; mt < 2; mt++)
#pragma unroll
                    for (int nt = 0; nt < 4; nt++)
                        mma16816(acc0[mt][nt], af[mt], &bf[nt >> 1][(nt & 1) * 2]);
            }
            // B1 pass
            {
                uint32_t bf[2][4];
#pragma unroll
                for (int np = 0; np < 2; np++) {
                    int row = wn * 32 + np * 16 + ((sub >> 1) << 3) + li;
                    int kb = (k0 + ((sub & 1) << 3)) * 2;
                    ldsm4(bf[np], tb + 2 * TILE_BYTES + swz128((uint32_t)(row * 128 + kb)));
                }
#pragma unroll
                for (int mt = 0; mt < 2; mt++)
#pragma unroll
                    for (int nt = 0; nt < 4; nt++)
                        mma16816(acc1[mt][nt], af[mt], &bf[nt >> 1][(nt & 1) * 2]);
            }
        }
    }
    asm volatile("cp.async.wait_group 0;" ::: "memory");

    // ---------------- fused epilogue ----------------
    const int l4 = lid >> 2, l2 = (lid & 3) * 2;
#pragma unroll
    for (int mt = 0; mt < 2; mt++) {
#pragma unroll
        for (int nt = 0; nt < 4; nt++) {
            const int gr = mBase + wm * 32 + mt * 16 + l4;
            const int gc = nBase + wn * 32 + nt * 8 + l2;
            const float* a0 = acc0[mt][nt];
            const float* a1 = acc1[mt][nt];
            float2 scv = make_float2(0.f, 0.f), b0 = scv, b1 = scv;
            if (MODE == 0) {
                b0 = *(const float2*)(e0 + gc);
                b1 = *(const float2*)(e1 + gc);
            } else {
                scv = *(const float2*)(sc + gc);
            }
#pragma unroll
            for (int half_ = 0; half_ < 2; half_++) {
                const int row = gr + half_ * 8;
                const size_t idx = (size_t)row * NDIM + gc;
                float v0x = a0[half_ * 2], v0y = a0[half_ * 2 + 1];
                float v1x = a1[half_ * 2], v1y = a1[half_ * 2 + 1];
                if (MODE == 0) {
                    *(float2*)(O0 + idx) = make_float2(v0x + b0.x, v0y + b0.y);
                    *(float2*)(O1 + idx) = make_float2(v1x + b1.x, v1y + b1.y);
                } else {
                    float2 pe0 = *(const float2*)(e0 + idx);
                    float2 pe1 = *(const float2*)(e1 + idx);
                    float2 hv  = *(const float2*)(hx + idx);
                    float dx = tanhf(pe0.x + v0x);
                    float dy = tanhf(pe0.y + v0y);
                    float gx = 1.0f / (1.0f + expf(-(pe1.x + v1x)));
                    float gy = 1.0f / (1.0f + expf(-(pe1.y + v1y)));
                    float ox = hv.x + scv.x * (gx * dx - hv.x);
                    float oy = hv.y + scv.y * (gy * dy - hv.y);
                    *(float2*)(O0 + idx) = make_float2(ox, oy);
                    if (MODE == 1) {
                        *(__half2*)(Oh + idx) = __floats2half2_rn(ox, oy);
                    } else {  // MODE 2
                        *(float2*)(O1 + idx) = make_float2(ox, oy);
                    }
                }
            }
        }
    }
}

// ---------------- launch ----------------
extern "C" void kernel_launch(void* const* d_in, const int* in_sizes, int n_in,
                              void* d_out, int out_size) {
    const float* x        = (const float*)d_in[0];
    const float* h_in     = (const float*)d_in[1];
    const float* log_tau  = (const float*)d_in[2];
    const float* W_in_w   = (const float*)d_in[3];
    const float* W_in_b   = (const float*)d_in[4];
    const float* W_rec_w  = (const float*)d_in[5];
    const float* W_gate_w = (const float*)d_in[6];
    const float* W_gate_b = (const float*)d_in[7];
    (void)in_sizes; (void)n_in;

    float *ph0, *ph1, *pid, *pgx, *psc;
    __half *phh0, *phh1, *pxh, *pwinh, *pwrech, *pwgxh, *pwghh;
    cudaGetSymbolAddress((void**)&ph0, g_h0);
    cudaGetSymbolAddress((void**)&ph1, g_h1);
    cudaGetSymbolAddress((void**)&phh0, g_hh0);
    cudaGetSymbolAddress((void**)&phh1, g_hh1);
    cudaGetSymbolAddress((void**)&pid, g_idrive);
    cudaGetSymbolAddress((void**)&pgx, g_gatex);
    cudaGetSymbolAddress((void**)&pxh, g_xh);
    cudaGetSymbolAddress((void**)&pwinh, g_winh);
    cudaGetSymbolAddress((void**)&pwrech, g_wrech);
    cudaGetSymbolAddress((void**)&pwgxh, g_wgxh);
    cudaGetSymbolAddress((void**)&pwghh, g_wghh);
    cudaGetSymbolAddress((void**)&psc, g_scale);

    cudaFuncSetAttribute(ltc_fused<0>, cudaFuncAttributeMaxDynamicSharedMemorySize, SMEM_TOTAL);
    cudaFuncSetAttribute(ltc_fused<1>, cudaFuncAttributeMaxDynamicSharedMemorySize, SMEM_TOTAL);
    cudaFuncSetAttribute(ltc_fused<2>, cudaFuncAttributeMaxDynamicSharedMemorySize, SMEM_TOTAL);

    const size_t n = (size_t)B_SZ * NDIM;

    // prep
    cudaMemcpyAsync(ph0, h_in, n * sizeof(float), cudaMemcpyDeviceToDevice, 0);
    scale_kernel<<<(NDIM + 255) / 256, 256>>>(log_tau, psc);
    tohalf_kernel<<<(int)((n / 4 + 255) / 256), 256>>>(x, pxh, (int)(n / 4));
    tohalf_kernel<<<(int)((n / 4 + 255) / 256), 256>>>(h_in, phh0, (int)(n / 4));
    tohalf_kernel<<<(NDIM * KDIM / 4 + 255) / 256, 256>>>(W_in_w, pwinh, NDIM * KDIM / 4);
    tohalf_kernel<<<(NDIM * KDIM / 4 + 255) / 256, 256>>>(W_rec_w, pwrech, NDIM * KDIM / 4);
    gate_split_half<<<(NDIM * KDIM / 4 + 255) / 256, 256>>>(W_gate_w, pwgxh, pwghh);

    dim3 grid(NDIM / BN, B_SZ / BM);  // (8, 64) = 512 CTAs

    // fused precompute: input_drive and gate_x in one pass over x
    ltc_fused<0><<<grid, NTHREADS, SMEM_TOTAL>>>(
        pxh, pwinh, pwgxh, W_in_b, W_gate_b, nullptr, nullptr, pid, pgx, nullptr);

    float*  hb[2]  = {ph0, ph1};
    __half* hhb[2] = {phh0, phh1};

    float* out = (float*)d_out;
    int dup = ((size_t)out_size >= 2 * n) ? 1 : 0;
    float* out2 = dup ? (out + n) : out;

    for (int s = 0; s < ODE_STEPS; s++) {
        const __half* hh = hhb[s & 1];
        const float*  he = hb[s & 1];
        if (s < ODE_STEPS - 1) {
            ltc_fused<1><<<grid, NTHREADS, SMEM_TOTAL>>>(
                hh, pwrech, pwghh, pid, pgx, he, psc,
                hb[(s + 1) & 1], nullptr, hhb[(s + 1) & 1]);
        } else {
            // last step: write final h straight into d_out (both copies)
            ltc_fused<2><<<grid, NTHREADS, SMEM_TOTAL>>>(
                hh, pwrech, pwghh, pid, pgx, he, psc,
                out, out2, nullptr);
        }
    }
}

// round 5
// speedup vs baseline: 6.1648x; 1.0552x over previous
#include <cuda_runtime.h>
#include <cuda_fp16.h>
#include <cstdint>
#include <math.h>

// ---------------- problem constants ----------------
#define B_SZ 8192
#define KDIM 1024
#define NDIM 1024
#define ODE_STEPS 6

// ---------------- GEMM config ----------------
#define BM 128
#define BN 128
#define KT 64                          // K elems per pipeline chunk (fp16: 128 B/row)
#define NCH (KDIM / KT)                // 16 chunks
#define STAGES 3
#define TILE_BYTES (BM * KT * 2)       // 16 KB per operand tile
#define STAGE_BYTES (3 * TILE_BYTES)   // A + B0 + B1 = 48 KB
#define SMEM_TOTAL (STAGES * STAGE_BYTES)  // 144 KB
#define NTHREADS 512

// ---------------- scratch (device globals; no runtime allocation) -----------
static __device__ float  g_h0[(size_t)B_SZ * NDIM];     // exact h ping
static __device__ float  g_h1[(size_t)B_SZ * NDIM];     // exact h pong
static __device__ __half g_hh0[(size_t)B_SZ * NDIM];    // fp16 h ping
static __device__ __half g_hh1[(size_t)B_SZ * NDIM];    // fp16 h pong
static __device__ __half g_idh[(size_t)B_SZ * NDIM];    // fp16 input_drive
static __device__ __half g_gxh[(size_t)B_SZ * NDIM];    // fp16 gate_x
static __device__ __half g_xh[(size_t)B_SZ * KDIM];     // fp16 x
static __device__ __half g_winh[(size_t)NDIM * KDIM];
static __device__ __half g_wrech[(size_t)NDIM * KDIM];
static __device__ __half g_wgxh[(size_t)NDIM * KDIM];
static __device__ __half g_wghh[(size_t)NDIM * KDIM];
static __device__ float  g_scale[NDIM];                 // (1/6)*exp(-log_tau)

// ---------------- helpers ----------------
__device__ __forceinline__ uint32_t swz128(uint32_t off) { return off ^ ((off >> 3) & 0x70); }

__device__ __forceinline__ void cp16(uint32_t s, const void* g) {
    asm volatile("cp.async.cg.shared.global [%0], [%1], 16;" :: "r"(s), "l"(g) : "memory");
}
__device__ __forceinline__ void ldsm4(uint32_t* r, uint32_t addr) {
    asm volatile("ldmatrix.sync.aligned.m8n8.x4.shared.b16 {%0,%1,%2,%3}, [%4];"
                 : "=r"(r[0]), "=r"(r[1]), "=r"(r[2]), "=r"(r[3]) : "r"(addr));
}
__device__ __forceinline__ void mma16816(float* d, const uint32_t* a, const uint32_t* b) {
    asm volatile(
        "mma.sync.aligned.m16n8k16.row.col.f32.f16.f16.f32 "
        "{%0,%1,%2,%3}, {%4,%5,%6,%7}, {%8,%9}, {%0,%1,%2,%3};"
        : "+f"(d[0]), "+f"(d[1]), "+f"(d[2]), "+f"(d[3])
        : "r"(a[0]), "r"(a[1]), "r"(a[2]), "r"(a[3]), "r"(b[0]), "r"(b[1]));
}

// ---------------- single merged prep kernel ----------------
#define L_X  ((B_SZ * KDIM) / 4)        // 2,097,152 float4 units
#define L_W  ((NDIM * KDIM) / 4)        // 262,144
#define P_O1 (L_X)
#define P_O2 (P_O1 + L_X)
#define P_O3 (P_O2 + L_W)
#define P_O4 (P_O3 + L_W)
#define P_O5 (P_O4 + L_W)
#define P_TOTAL (P_O5 + NDIM / 4)

__global__ void prep_all(const float* __restrict__ x, const float* __restrict__ h,
                         const float* __restrict__ win, const float* __restrict__ wrec,
                         const float* __restrict__ wg, const float* __restrict__ log_tau,
                         __half* __restrict__ xh, __half* __restrict__ hh,
                         __half* __restrict__ winh, __half* __restrict__ wrech,
                         __half* __restrict__ wgxh, __half* __restrict__ wghh,
                         float* __restrict__ scale) {
    int i = blockIdx.x * blockDim.x + threadIdx.x;
    if (i < P_O1) {
        float4 v = ((const float4*)x)[i];
        ((__half2*)xh)[2 * i]     = __floats2half2_rn(v.x, v.y);
        ((__half2*)xh)[2 * i + 1] = __floats2half2_rn(v.z, v.w);
    } else if (i < P_O2) {
        int j = i - P_O1;
        float4 v = ((const float4*)h)[j];
        ((__half2*)hh)[2 * j]     = __floats2half2_rn(v.x, v.y);
        ((__half2*)hh)[2 * j + 1] = __floats2half2_rn(v.z, v.w);
    } else if (i < P_O3) {
        int j = i - P_O2;
        float4 v = ((const float4*)win)[j];
        ((__half2*)winh)[2 * j]     = __floats2half2_rn(v.x, v.y);
        ((__half2*)winh)[2 * j + 1] = __floats2half2_rn(v.z, v.w);
    } else if (i < P_O4) {
        int j = i - P_O3;
        float4 v = ((const float4*)wrec)[j];
        ((__half2*)wrech)[2 * j]     = __floats2half2_rn(v.x, v.y);
        ((__half2*)wrech)[2 * j + 1] = __floats2half2_rn(v.z, v.w);
    } else if (i < P_O5) {
        int j = i - P_O4;
        int i4 = j * 4;
        int row = i4 >> 10, col = i4 & 1023;
        const float4 vx = *(const float4*)(wg + (size_t)row * 2048 + col);
        const float4 vh = *(const float4*)(wg + (size_t)row * 2048 + 1024 + col);
        ((__half2*)wgxh)[2 * j]     = __floats2half2_rn(vx.x, vx.y);
        ((__half2*)wgxh)[2 * j + 1] = __floats2half2_rn(vx.z, vx.w);
        ((__half2*)wghh)[2 * j]     = __floats2half2_rn(vh.x, vh.y);
        ((__half2*)wghh)[2 * j + 1] = __floats2half2_rn(vh.z, vh.w);
    } else if (i < P_TOTAL) {
        int j = i - P_O5;
        float4 v = ((const float4*)log_tau)[j];
        float4 o;
        o.x = (1.0f / 6.0f) * expf(-v.x);
        o.y = (1.0f / 6.0f) * expf(-v.y);
        o.z = (1.0f / 6.0f) * expf(-v.z);
        o.w = (1.0f / 6.0f) * expf(-v.w);
        ((float4*)scale)[j] = o;
    }
}

// ---------------- dual fp16 tensor-core GEMM with fully fused step ----------
// acc0[m,n] = sum_k A[m,k]*W0[n,k];  acc1[m,n] = sum_k A[m,k]*W1[n,k]
// MODE 0 (precompute): Oh0 = half(acc0 + b0[n]);  Oh1 = half(acc1 + b1[n])
// MODE 1 (ODE step):   drive = tanh(eh0[idx]+acc0); gate = sigmoid(eh1[idx]+acc1);
//                      o = hx + sc[n]*(gate*drive - hx);  Of = o; Oh0 = half(o)
// MODE 2 (last step):  same as 1 but Of = o and Of2 = o (duplicated fp32 output)
template <int MODE>
__global__ void __launch_bounds__(NTHREADS, 1)
ltc_fused(const __half* __restrict__ A, const __half* __restrict__ W0,
          const __half* __restrict__ W1,
          const __half* __restrict__ eh0, const __half* __restrict__ eh1,
          const float* __restrict__ b0p, const float* __restrict__ b1p,
          const float* __restrict__ hx, const float* __restrict__ sc,
          float* __restrict__ Of, float* __restrict__ Of2,
          __half* __restrict__ Oh0, __half* __restrict__ Oh1) {
    extern __shared__ char dsm[];
    const uint32_t sbase = (uint32_t)__cvta_generic_to_shared(dsm);
    const int tid = threadIdx.x;
    const int wid = tid >> 5, lid = tid & 31;
    const int wm = wid >> 2, wn = wid & 3;      // 4x4 warp grid; warp tile 32x32
    const int mBase = blockIdx.y * BM;
    const int nBase = blockIdx.x * BN;

    auto load_chunk = [&](int c) {
        const uint32_t st = sbase + (c % STAGES) * STAGE_BYTES;
        const __half* ga  = A  + (size_t)mBase * KDIM + c * KT;
        const __half* gb0 = W0 + (size_t)nBase * KDIM + c * KT;
        const __half* gb1 = W1 + (size_t)nBase * KDIM + c * KT;
#pragma unroll
        for (int i = 0; i < 2; i++) {
            int t = tid + i * NTHREADS;          // 0..1023
            int row = t >> 3, cg = t & 7;
            uint32_t sw = swz128((uint32_t)(row * 128 + cg * 16));
            size_t go = (size_t)row * KDIM + cg * 8;
            cp16(st + sw, ga + go);
            cp16(st + TILE_BYTES + sw, gb0 + go);
            cp16(st + 2 * TILE_BYTES + sw, gb1 + go);
        }
        asm volatile("cp.async.commit_group;" ::: "memory");
    };

    float acc0[2][4][4], acc1[2][4][4];
#pragma unroll
    for (int mt = 0; mt < 2; mt++)
#pragma unroll
        for (int nt = 0; nt < 4; nt++)
#pragma unroll
            for (int e = 0; e < 4; e++) { acc0[mt][nt][e] = 0.0f; acc1[mt][nt][e] = 0.0f; }

    load_chunk(0);
    load_chunk(1);

    const int sub = lid >> 3, li = lid & 7;

    for (int kt = 0; kt < NCH; kt++) {
        asm volatile("cp.async.wait_group 1;" ::: "memory");
        __syncthreads();
        if (kt + 2 < NCH) load_chunk(kt + 2);
        else asm volatile("cp.async.commit_group;" ::: "memory");

        const uint32_t tb = sbase + (kt % STAGES) * STAGE_BYTES;
#pragma unroll
        for (int ks = 0; ks < 4; ks++) {
            const int k0 = ks * 16;
            uint32_t af[2][4];
#pragma unroll
            for (int mt = 0; mt < 2; mt++) {
                int row = wm * 32 + mt * 16 + ((sub & 1) << 3) + li;
                int kb = (k0 + ((sub >> 1) << 3)) * 2;
                ldsm4(af[mt], tb + swz128((uint32_t)(row * 128 + kb)));
            }
            {
                uint32_t bf[2][4];
#pragma unroll
                for (int np = 0; np < 2; np++) {
                    int row = wn * 32 + np * 16 + ((sub >> 1) << 3) + li;
                    int kb = (k0 + ((sub & 1) << 3)) * 2;
                    ldsm4(bf[np], tb + TILE_BYTES + swz128((uint32_t)(row * 128 + kb)));
                }
#pragma unroll
                for (int mt = 0; mt < 2; mt++)
#pragma unroll
                    for (int nt = 0; nt < 4; nt++)
                        mma16816(acc0[mt][nt], af[mt], &bf[nt >> 1][(nt & 1) * 2]);
            }
            {
                uint32_t bf[2][4];
#pragma unroll
                for (int np = 0; np < 2; np++) {
                    int row = wn * 32 + np * 16 + ((sub >> 1) << 3) + li;
                    int kb = (k0 + ((sub & 1) << 3)) * 2;
                    ldsm4(bf[np], tb + 2 * TILE_BYTES + swz128((uint32_t)(row * 128 + kb)));
                }
#pragma unroll
                for (int mt = 0; mt < 2; mt++)
#pragma unroll
                    for (int nt = 0; nt < 4; nt++)
                        mma16816(acc1[mt][nt], af[mt], &bf[nt >> 1][(nt & 1) * 2]);
            }
        }
    }
    asm volatile("cp.async.wait_group 0;" ::: "memory");

    // ---------------- fused epilogue ----------------
    const int l4 = lid >> 2, l2 = (lid & 3) * 2;
#pragma unroll
    for (int mt = 0; mt < 2; mt++) {
#pragma unroll
        for (int nt = 0; nt < 4; nt++) {
            const int gr = mBase + wm * 32 + mt * 16 + l4;
            const int gc = nBase + wn * 32 + nt * 8 + l2;
            const float* a0 = acc0[mt][nt];
            const float* a1 = acc1[mt][nt];
            float2 scv = make_float2(0.f, 0.f), bb0 = scv, bb1 = scv;
            if (MODE == 0) {
                bb0 = *(const float2*)(b0p + gc);
                bb1 = *(const float2*)(b1p + gc);
            } else {
                scv = *(const float2*)(sc + gc);
            }
#pragma unroll
            for (int half_ = 0; half_ < 2; half_++) {
                const int row = gr + half_ * 8;
                const size_t idx = (size_t)row * NDIM + gc;
                float v0x = a0[half_ * 2], v0y = a0[half_ * 2 + 1];
                float v1x = a1[half_ * 2], v1y = a1[half_ * 2 + 1];
                if (MODE == 0) {
                    *(__half2*)(Oh0 + idx) = __floats2half2_rn(v0x + bb0.x, v0y + bb0.y);
                    *(__half2*)(Oh1 + idx) = __floats2half2_rn(v1x + bb1.x, v1y + bb1.y);
                } else {
                    float2 pe0 = __half22float2(*(const __half2*)(eh0 + idx));
                    float2 pe1 = __half22float2(*(const __half2*)(eh1 + idx));
                    float2 hv  = *(const float2*)(hx + idx);
                    float dx = tanhf(pe0.x + v0x);
                    float dy = tanhf(pe0.y + v0y);
                    float gx = 1.0f / (1.0f + __expf(-(pe1.x + v1x)));
                    float gy = 1.0f / (1.0f + __expf(-(pe1.y + v1y)));
                    float ox = hv.x + scv.x * (gx * dx - hv.x);
                    float oy = hv.y + scv.y * (gy * dy - hv.y);
                    *(float2*)(Of + idx) = make_float2(ox, oy);
                    if (MODE == 1) {
                        *(__half2*)(Oh0 + idx) = __floats2half2_rn(ox, oy);
                    } else {  // MODE 2
                        *(float2*)(Of2 + idx) = make_float2(ox, oy);
                    }
                }
            }
        }
    }
}

// ---------------- launch ----------------
extern "C" void kernel_launch(void* const* d_in, const int* in_sizes, int n_in,
                              void* d_out, int out_size) {
    const float* x        = (const float*)d_in[0];
    const float* h_in     = (const float*)d_in[1];
    const float* log_tau  = (const float*)d_in[2];
    const float* W_in_w   = (const float*)d_in[3];
    const float* W_in_b   = (const float*)d_in[4];
    const float* W_rec_w  = (const float*)d_in[5];
    const float* W_gate_w = (const float*)d_in[6];
    const float* W_gate_b = (const float*)d_in[7];
    (void)in_sizes; (void)n_in;

    float *ph0, *ph1, *psc;
    __half *phh0, *phh1, *pidh, *pgxh, *pxh, *pwinh, *pwrech, *pwgxh, *pwghh;
    cudaGetSymbolAddress((void**)&ph0, g_h0);
    cudaGetSymbolAddress((void**)&ph1, g_h1);
    cudaGetSymbolAddress((void**)&phh0, g_hh0);
    cudaGetSymbolAddress((void**)&phh1, g_hh1);
    cudaGetSymbolAddress((void**)&pidh, g_idh);
    cudaGetSymbolAddress((void**)&pgxh, g_gxh);
    cudaGetSymbolAddress((void**)&pxh, g_xh);
    cudaGetSymbolAddress((void**)&pwinh, g_winh);
    cudaGetSymbolAddress((void**)&pwrech, g_wrech);
    cudaGetSymbolAddress((void**)&pwgxh, g_wgxh);
    cudaGetSymbolAddress((void**)&pwghh, g_wghh);
    cudaGetSymbolAddress((void**)&psc, g_scale);

    cudaFuncSetAttribute(ltc_fused<0>, cudaFuncAttributeMaxDynamicSharedMemorySize, SMEM_TOTAL);
    cudaFuncSetAttribute(ltc_fused<1>, cudaFuncAttributeMaxDynamicSharedMemorySize, SMEM_TOTAL);
    cudaFuncSetAttribute(ltc_fused<2>, cudaFuncAttributeMaxDynamicSharedMemorySize, SMEM_TOTAL);

    const size_t n = (size_t)B_SZ * NDIM;

    // single merged prep launch (casts + gate split + scale)
    prep_all<<<(P_TOTAL + 255) / 256, 256>>>(
        x, h_in, W_in_w, W_rec_w, W_gate_w, log_tau,
        pxh, phh0, pwinh, pwrech, pwgxh, pwghh, psc);

    dim3 grid(NDIM / BN, B_SZ / BM);  // (8, 64) = 512 CTAs

    // fused precompute: input_drive and gate_x (fp16) in one pass over x
    ltc_fused<0><<<grid, NTHREADS, SMEM_TOTAL>>>(
        pxh, pwinh, pwgxh, nullptr, nullptr, W_in_b, W_gate_b,
        nullptr, nullptr, nullptr, nullptr, pidh, pgxh);

    float* out = (float*)d_out;
    int dup = ((size_t)out_size >= 2 * n) ? 1 : 0;
    float* out2 = dup ? (out + n) : out;

    const float*  hf_cur = h_in;   // fp32 state source (read-only for step 0)
    const __half* hh_cur = phh0;
    for (int s = 0; s < ODE_STEPS; s++) {
        float*  tgt_f = (s & 1) ? ph1 : ph0;
        __half* tgt_h = (s & 1) ? phh0 : phh1;
        if (s < ODE_STEPS - 1) {
            ltc_fused<1><<<grid, NTHREADS, SMEM_TOTAL>>>(
                hh_cur, pwrech, pwghh, pidh, pgxh, nullptr, nullptr,
                hf_cur, psc, tgt_f, nullptr, tgt_h, nullptr);
            hf_cur = tgt_f;
            hh_cur = tgt_h;
        } else {
            // last step: write final h straight into d_out (both copies)
            ltc_fused<2><<<grid, NTHREADS, SMEM_TOTAL>>>(
                hh_cur, pwrech, pwghh, pidh, pgxh, nullptr, nullptr,
                hf_cur, psc, out, out2, nullptr, nullptr);
        }
    }
}

// round 6
// speedup vs baseline: 7.6851x; 1.2466x over previous
#include <cuda_runtime.h>
#include <cuda_fp16.h>
#include <cstdint>
#include <math.h>

// ---------------- problem constants ----------------
#define B_SZ 8192
#define KDIM 1024
#define NDIM 1024
#define ODE_STEPS 6

// ---------------- GEMM config ----------------
#define BM 128
#define BN 64
#define KT 64                            // K elems per chunk (fp16: 128 B/row)
#define NCH (KDIM / KT)                  // 16 chunks
#define STAGES 3
#define TILE_A_BYTES (BM * KT * 2)       // 16 KB
#define TILE_B_BYTES (BN * KT * 2)       // 8 KB
#define STAGE_BYTES (TILE_A_BYTES + 2 * TILE_B_BYTES)   // 32 KB
#define SMEM_TOTAL (STAGES * STAGE_BYTES)               // 96 KB
#define NTHREADS 256

// ---------------- scratch (device globals; no runtime allocation) -----------
static __device__ float  g_h0[(size_t)B_SZ * NDIM];
static __device__ float  g_h1[(size_t)B_SZ * NDIM];
static __device__ __half g_hh0[(size_t)B_SZ * NDIM];
static __device__ __half g_hh1[(size_t)B_SZ * NDIM];
static __device__ __half g_idh[(size_t)B_SZ * NDIM];    // fp16 input_drive
static __device__ __half g_gxh[(size_t)B_SZ * NDIM];    // fp16 gate_x
static __device__ __half g_xh[(size_t)B_SZ * KDIM];
static __device__ __half g_winh[(size_t)NDIM * KDIM];
static __device__ __half g_wrech[(size_t)NDIM * KDIM];
static __device__ __half g_wgxh[(size_t)NDIM * KDIM];
static __device__ __half g_wghh[(size_t)NDIM * KDIM];
static __device__ float  g_scale[NDIM];

// ---------------- helpers ----------------
__device__ __forceinline__ uint32_t swz128(uint32_t off) { return off ^ ((off >> 3) & 0x70); }

__device__ __forceinline__ void cp16(uint32_t s, const void* g) {
    asm volatile("cp.async.cg.shared.global [%0], [%1], 16;" :: "r"(s), "l"(g) : "memory");
}
__device__ __forceinline__ void ldsm4(uint32_t* r, uint32_t addr) {
    asm volatile("ldmatrix.sync.aligned.m8n8.x4.shared.b16 {%0,%1,%2,%3}, [%4];"
                 : "=r"(r[0]), "=r"(r[1]), "=r"(r[2]), "=r"(r[3]) : "r"(addr));
}
__device__ __forceinline__ void mma16816(float* d, const uint32_t* a, const uint32_t* b) {
    asm volatile(
        "mma.sync.aligned.m16n8k16.row.col.f32.f16.f16.f32 "
        "{%0,%1,%2,%3}, {%4,%5,%6,%7}, {%8,%9}, {%0,%1,%2,%3};"
        : "+f"(d[0]), "+f"(d[1]), "+f"(d[2]), "+f"(d[3])
        : "r"(a[0]), "r"(a[1]), "r"(a[2]), "r"(a[3]), "r"(b[0]), "r"(b[1]));
}

// ---------------- single merged prep kernel ----------------
#define L_X  ((B_SZ * KDIM) / 4)
#define L_W  ((NDIM * KDIM) / 4)
#define P_O1 (L_X)
#define P_O2 (P_O1 + L_X)
#define P_O3 (P_O2 + L_W)
#define P_O4 (P_O3 + L_W)
#define P_O5 (P_O4 + L_W)
#define P_TOTAL (P_O5 + NDIM / 4)

__global__ void prep_all(const float* __restrict__ x, const float* __restrict__ h,
                         const float* __restrict__ win, const float* __restrict__ wrec,
                         const float* __restrict__ wg, const float* __restrict__ log_tau,
                         __half* __restrict__ xh, __half* __restrict__ hh,
                         __half* __restrict__ winh, __half* __restrict__ wrech,
                         __half* __restrict__ wgxh, __half* __restrict__ wghh,
                         float* __restrict__ scale) {
    int i = blockIdx.x * blockDim.x + threadIdx.x;
    if (i < P_O1) {
        float4 v = ((const float4*)x)[i];
        ((__half2*)xh)[2 * i]     = __floats2half2_rn(v.x, v.y);
        ((__half2*)xh)[2 * i + 1] = __floats2half2_rn(v.z, v.w);
    } else if (i < P_O2) {
        int j = i - P_O1;
        float4 v = ((const float4*)h)[j];
        ((__half2*)hh)[2 * j]     = __floats2half2_rn(v.x, v.y);
        ((__half2*)hh)[2 * j + 1] = __floats2half2_rn(v.z, v.w);
    } else if (i < P_O3) {
        int j = i - P_O2;
        float4 v = ((const float4*)win)[j];
        ((__half2*)winh)[2 * j]     = __floats2half2_rn(v.x, v.y);
        ((__half2*)winh)[2 * j + 1] = __floats2half2_rn(v.z, v.w);
    } else if (i < P_O4) {
        int j = i - P_O3;
        float4 v = ((const float4*)wrec)[j];
        ((__half2*)wrech)[2 * j]     = __floats2half2_rn(v.x, v.y);
        ((__half2*)wrech)[2 * j + 1] = __floats2half2_rn(v.z, v.w);
    } else if (i < P_O5) {
        int j = i - P_O4;
        int i4 = j * 4;
        int row = i4 >> 10, col = i4 & 1023;
        const float4 vx = *(const float4*)(wg + (size_t)row * 2048 + col);
        const float4 vh = *(const float4*)(wg + (size_t)row * 2048 + 1024 + col);
        ((__half2*)wgxh)[2 * j]     = __floats2half2_rn(vx.x, vx.y);
        ((__half2*)wgxh)[2 * j + 1] = __floats2half2_rn(vx.z, vx.w);
        ((__half2*)wghh)[2 * j]     = __floats2half2_rn(vh.x, vh.y);
        ((__half2*)wghh)[2 * j + 1] = __floats2half2_rn(vh.z, vh.w);
    } else if (i < P_TOTAL) {
        int j = i - P_O5;
        float4 v = ((const float4*)log_tau)[j];
        float4 o;
        o.x = (1.0f / 6.0f) * expf(-v.x);
        o.y = (1.0f / 6.0f) * expf(-v.y);
        o.z = (1.0f / 6.0f) * expf(-v.z);
        o.w = (1.0f / 6.0f) * expf(-v.w);
        ((float4*)scale)[j] = o;
    }
}

// ---------------- dual fp16 tensor-core GEMM with fully fused step ----------
// MODE 0: Oh0 = half(acc0 + b0[n]);  Oh1 = half(acc1 + b1[n])
// MODE 1: drive=tanh(eh0+acc0); gate=sigmoid(eh1+acc1);
//         o = hx + sc[n]*(gate*drive - hx);  Of = o; Oh0 = half(o)
// MODE 2: same as 1 but Of = o and Of2 = o
template <int MODE>
__global__ void __launch_bounds__(NTHREADS, 2)
ltc_fused(const __half* __restrict__ A, const __half* __restrict__ W0,
          const __half* __restrict__ W1,
          const __half* __restrict__ eh0, const __half* __restrict__ eh1,
          const float* __restrict__ b0p, const float* __restrict__ b1p,
          const float* __restrict__ hx, const float* __restrict__ sc,
          float* __restrict__ Of, float* __restrict__ Of2,
          __half* __restrict__ Oh0, __half* __restrict__ Oh1) {
    extern __shared__ char dsm[];
    const uint32_t sbase = (uint32_t)__cvta_generic_to_shared(dsm);
    const int tid = threadIdx.x;
    const int wid = tid >> 5, lid = tid & 31;
    const int wm = wid >> 1, wn = wid & 1;      // 4x2 warp grid; warp tile 32x32
    const int mBase = blockIdx.y * BM;
    const int nBase = blockIdx.x * BN;

    auto load_chunk = [&](int c) {
        const uint32_t st = sbase + (c % STAGES) * STAGE_BYTES;
        const __half* ga  = A  + (size_t)mBase * KDIM + c * KT;
        const __half* gb0 = W0 + (size_t)nBase * KDIM + c * KT;
        const __half* gb1 = W1 + (size_t)nBase * KDIM + c * KT;
        // A: 128 rows x 8 groups = 1024 cp16
#pragma unroll
        for (int i = 0; i < 4; i++) {
            int t = tid + i * NTHREADS;
            int row = t >> 3, cg = t & 7;
            uint32_t sw = swz128((uint32_t)(row * 128 + cg * 16));
            cp16(st + sw, ga + (size_t)row * KDIM + cg * 8);
        }
        // B0/B1: 64 rows x 8 groups = 512 cp16 each
#pragma unroll
        for (int i = 0; i < 2; i++) {
            int t = tid + i * NTHREADS;
            int row = t >> 3, cg = t & 7;
            uint32_t sw = swz128((uint32_t)(row * 128 + cg * 16));
            size_t go = (size_t)row * KDIM + cg * 8;
            cp16(st + TILE_A_BYTES + sw, gb0 + go);
            cp16(st + TILE_A_BYTES + TILE_B_BYTES + sw, gb1 + go);
        }
        asm volatile("cp.async.commit_group;" ::: "memory");
    };

    float acc0[2][4][4], acc1[2][4][4];
#pragma unroll
    for (int mt = 0; mt < 2; mt++)
#pragma unroll
        for (int nt = 0; nt < 4; nt++)
#pragma unroll
            for (int e = 0; e < 4; e++) { acc0[mt][nt][e] = 0.0f; acc1[mt][nt][e] = 0.0f; }

    load_chunk(0);
    load_chunk(1);

    const int sub = lid >> 3, li = lid & 7;

    for (int kt = 0; kt < NCH; kt++) {
        asm volatile("cp.async.wait_group 1;" ::: "memory");
        __syncthreads();
        if (kt + 2 < NCH) load_chunk(kt + 2);
        else asm volatile("cp.async.commit_group;" ::: "memory");

        const uint32_t tb = sbase + (kt % STAGES) * STAGE_BYTES;
#pragma unroll
        for (int ks = 0; ks < 4; ks++) {
            const int k0 = ks * 16;
            uint32_t af[2][4];
#pragma unroll
            for (int mt = 0; mt < 2; mt++) {
                int row = wm * 32 + mt * 16 + ((sub & 1) << 3) + li;
                int kb = (k0 + ((sub >> 1) << 3)) * 2;
                ldsm4(af[mt], tb + swz128((uint32_t)(row * 128 + kb)));
            }
            {
                uint32_t bf[2][4];
#pragma unroll
                for (int np = 0; np < 2; np++) {
                    int row = wn * 32 + np * 16 + ((sub >> 1) << 3) + li;
                    int kb = (k0 + ((sub & 1) << 3)) * 2;
                    ldsm4(bf[np], tb + TILE_A_BYTES + swz128((uint32_t)(row * 128 + kb)));
                }
#pragma unroll
                for (int mt = 0; mt < 2; mt++)
#pragma unroll
                    for (int nt = 0; nt < 4; nt++)
                        mma16816(acc0[mt][nt], af[mt], &bf[nt >> 1][(nt & 1) * 2]);
            }
            {
                uint32_t bf[2][4];
#pragma unroll
                for (int np = 0; np < 2; np++) {
                    int row = wn * 32 + np * 16 + ((sub >> 1) << 3) + li;
                    int kb = (k0 + ((sub & 1) << 3)) * 2;
                    ldsm4(bf[np], tb + TILE_A_BYTES + TILE_B_BYTES + swz128((uint32_t)(row * 128 + kb)));
                }
#pragma unroll
                for (int mt = 0; mt < 2; mt++)
#pragma unroll
                    for (int nt = 0; nt < 4; nt++)
                        mma16816(acc1[mt][nt], af[mt], &bf[nt >> 1][(nt & 1) * 2]);
            }
        }
    }
    asm volatile("cp.async.wait_group 0;" ::: "memory");

    // ---------------- fused epilogue ----------------
    const int l4 = lid >> 2, l2 = (lid & 3) * 2;
#pragma unroll
    for (int mt = 0; mt < 2; mt++) {
#pragma unroll
        for (int nt = 0; nt < 4; nt++) {
            const int gr = mBase + wm * 32 + mt * 16 + l4;
            const int gc = nBase + wn * 32 + nt * 8 + l2;
            const float* a0 = acc0[mt][nt];
            const float* a1 = acc1[mt][nt];
            float2 scv = make_float2(0.f, 0.f), bb0 = scv, bb1 = scv;
            if (MODE == 0) {
                bb0 = *(const float2*)(b0p + gc);
                bb1 = *(const float2*)(b1p + gc);
            } else {
                scv = *(const float2*)(sc + gc);
            }
#pragma unroll
            for (int half_ = 0; half_ < 2; half_++) {
                const int row = gr + half_ * 8;
                const size_t idx = (size_t)row * NDIM + gc;
                float v0x = a0[half_ * 2], v0y = a0[half_ * 2 + 1];
                float v1x = a1[half_ * 2], v1y = a1[half_ * 2 + 1];
                if (MODE == 0) {
                    *(__half2*)(Oh0 + idx) = __floats2half2_rn(v0x + bb0.x, v0y + bb0.y);
                    *(__half2*)(Oh1 + idx) = __floats2half2_rn(v1x + bb1.x, v1y + bb1.y);
                } else {
                    float2 pe0 = __half22float2(*(const __half2*)(eh0 + idx));
                    float2 pe1 = __half22float2(*(const __half2*)(eh1 + idx));
                    float2 hv  = *(const float2*)(hx + idx);
                    float dx = tanhf(pe0.x + v0x);
                    float dy = tanhf(pe0.y + v0y);
                    float gx = 1.0f / (1.0f + __expf(-(pe1.x + v1x)));
                    float gy = 1.0f / (1.0f + __expf(-(pe1.y + v1y)));
                    float ox = hv.x + scv.x * (gx * dx - hv.x);
                    float oy = hv.y + scv.y * (gy * dy - hv.y);
                    *(float2*)(Of + idx) = make_float2(ox, oy);
                    if (MODE == 1) {
                        *(__half2*)(Oh0 + idx) = __floats2half2_rn(ox, oy);
                    } else {  // MODE 2
                        *(float2*)(Of2 + idx) = make_float2(ox, oy);
                    }
                }
            }
        }
    }
}

// ---------------- launch ----------------
extern "C" void kernel_launch(void* const* d_in, const int* in_sizes, int n_in,
                              void* d_out, int out_size) {
    const float* x        = (const float*)d_in[0];
    const float* h_in     = (const float*)d_in[1];
    const float* log_tau  = (const float*)d_in[2];
    const float* W_in_w   = (const float*)d_in[3];
    const float* W_in_b   = (const float*)d_in[4];
    const float* W_rec_w  = (const float*)d_in[5];
    const float* W_gate_w = (const float*)d_in[6];
    const float* W_gate_b = (const float*)d_in[7];
    (void)in_sizes; (void)n_in;

    float *ph0, *ph1, *psc;
    __half *phh0, *phh1, *pidh, *pgxh, *pxh, *pwinh, *pwrech, *pwgxh, *pwghh;
    cudaGetSymbolAddress((void**)&ph0, g_h0);
    cudaGetSymbolAddress((void**)&ph1, g_h1);
    cudaGetSymbolAddress((void**)&phh0, g_hh0);
    cudaGetSymbolAddress((void**)&phh1, g_hh1);
    cudaGetSymbolAddress((void**)&pidh, g_idh);
    cudaGetSymbolAddress((void**)&pgxh, g_gxh);
    cudaGetSymbolAddress((void**)&pxh, g_xh);
    cudaGetSymbolAddress((void**)&pwinh, g_winh);
    cudaGetSymbolAddress((void**)&pwrech, g_wrech);
    cudaGetSymbolAddress((void**)&pwgxh, g_wgxh);
    cudaGetSymbolAddress((void**)&pwghh, g_wghh);
    cudaGetSymbolAddress((void**)&psc, g_scale);

    cudaFuncSetAttribute(ltc_fused<0>, cudaFuncAttributeMaxDynamicSharedMemorySize, SMEM_TOTAL);
    cudaFuncSetAttribute(ltc_fused<1>, cudaFuncAttributeMaxDynamicSharedMemorySize, SMEM_TOTAL);
    cudaFuncSetAttribute(ltc_fused<2>, cudaFuncAttributeMaxDynamicSharedMemorySize, SMEM_TOTAL);

    const size_t n = (size_t)B_SZ * NDIM;

    prep_all<<<(P_TOTAL + 255) / 256, 256>>>(
        x, h_in, W_in_w, W_rec_w, W_gate_w, log_tau,
        pxh, phh0, pwinh, pwrech, pwgxh, pwghh, psc);

    dim3 grid(NDIM / BN, B_SZ / BM);  // (16, 64) = 1024 CTAs

    ltc_fused<0><<<grid, NTHREADS, SMEM_TOTAL>>>(
        pxh, pwinh, pwgxh, nullptr, nullptr, W_in_b, W_gate_b,
        nullptr, nullptr, nullptr, nullptr, pidh, pgxh);

    float* out = (float*)d_out;
    int dup = ((size_t)out_size >= 2 * n) ? 1 : 0;
    float* out2 = dup ? (out + n) : out;

    const float*  hf_cur = h_in;
    const __half* hh_cur = phh0;
    for (int s = 0; s < ODE_STEPS; s++) {
        float*  tgt_f = (s & 1) ? ph1 : ph0;
        __half* tgt_h = (s & 1) ? phh0 : phh1;
        if (s < ODE_STEPS - 1) {
            ltc_fused<1><<<grid, NTHREADS, SMEM_TOTAL>>>(
                hh_cur, pwrech, pwghh, pidh, pgxh, nullptr, nullptr,
                hf_cur, psc, tgt_f, nullptr, tgt_h, nullptr);
            hf_cur = tgt_f;
            hh_cur = tgt_h;
        } else {
            ltc_fused<2><<<grid, NTHREADS, SMEM_TOTAL>>>(
                hh_cur, pwrech, pwghh, pidh, pgxh, nullptr, nullptr,
                hf_cur, psc, out, out2, nullptr, nullptr);
        }
    }
}